// round 1
// baseline (speedup 1.0000x reference)
#include <cuda_runtime.h>
#include <math.h>
#include <stdint.h>

#define Bc 2
#define Sc 4096
#define Dc 768
#define Hc 12
#define DHc 64
#define Lc 2
#define Fc 3072
#define Cc 256
#define NBc 16
#define W3 (3*Cc)
#define NEGF (-1000000000.0f)

// ---------------- scratch (device globals; no allocation allowed) ----------------
__device__ float g_h  [(size_t)Bc*Sc*Dc];
__device__ float g_q  [(size_t)Bc*Sc*Dc];
__device__ float g_k  [(size_t)Bc*Sc*Dc];
__device__ float g_v  [(size_t)Bc*Sc*Dc];
__device__ float g_ctx[(size_t)Bc*Sc*Dc];
__device__ float g_att[(size_t)Bc*Sc*Dc];
__device__ float g_mid[(size_t)Bc*Sc*Fc];
__device__ float g_sc [(size_t)Bc*Hc*NBc*Cc*W3];   // sliding scores/probs
__device__ float g_gs [(size_t)Bc*Hc*Sc];          // global-key score/prob
__device__ float g_q0 [Bc*Dc];
__device__ float g_o0 [Bc*Dc];
__device__ float g_a0 [Bc*Dc];
__device__ float g_h0 [Bc*Dc];
__device__ float g_f0 [Bc*Dc];
__device__ float g_m0 [Bc*Fc];

__device__ __forceinline__ float gelu_exact(float x) {
    return 0.5f * x * (1.0f + erff(x * 0.70710678118654752f));
}

// ---------------- embedding gather ----------------
__global__ void embed_gather(const int* __restrict__ ids, const float* __restrict__ tok,
                             const float* __restrict__ pos, float* __restrict__ out) {
    long i = (long)blockIdx.x * 256 + threadIdx.x;
    if (i >= (long)Bc*Sc*Dc) return;
    long bs = i / Dc; int d = (int)(i % Dc); int s = (int)(bs % Sc);
    out[i] = tok[(size_t)ids[bs]*Dc + d] + pos[(size_t)s*Dc + d];
}

// ---------------- LayerNorm (+optional residual); one block per row, D=768 ----------------
__global__ void ln_kernel(const float* __restrict__ x, long xs,
                          const float* __restrict__ res, long rs,
                          const float* __restrict__ g, const float* __restrict__ bb,
                          float* __restrict__ out, long os) {
    __shared__ float red[256];
    int row = blockIdx.x, t = threadIdx.x;
    const float* xr = x + (size_t)row * xs;
    float v0 = xr[t], v1 = xr[t+256], v2 = xr[t+512];
    if (res) {
        const float* rr = res + (size_t)row * rs;
        v0 += rr[t]; v1 += rr[t+256]; v2 += rr[t+512];
    }
    float s = v0 + v1 + v2;
    red[t] = s; __syncthreads();
    for (int o = 128; o > 0; o >>= 1) { if (t < o) red[t] += red[t+o]; __syncthreads(); }
    float mean = red[0] * (1.0f/768.0f); __syncthreads();
    float d0 = v0-mean, d1 = v1-mean, d2 = v2-mean;
    red[t] = d0*d0 + d1*d1 + d2*d2; __syncthreads();
    for (int o = 128; o > 0; o >>= 1) { if (t < o) red[t] += red[t+o]; __syncthreads(); }
    float rstd = rsqrtf(red[0] * (1.0f/768.0f) + 1e-5f);
    float* orow = out + (size_t)row * os;
    orow[t]     = d0*rstd*g[t]     + bb[t];
    orow[t+256] = d1*rstd*g[t+256] + bb[t+256];
    orow[t+512] = d2*rstd*g[t+512] + bb[t+512];
}

// ---------------- big GEMM: C = act(alpha*(A@W + bias)); 128x128x8, 256 thr ----------------
__global__ __launch_bounds__(256)
void gemm_kernel(const float* __restrict__ A, const float* __restrict__ Wm,
                 const float* __restrict__ bias, float* __restrict__ Cout,
                 int M, int N, int K, float alpha, int act) {
    __shared__ float As[8][128];
    __shared__ float Bs[8][128];
    int tid = threadIdx.x;
    int bm = blockIdx.y * 128, bn = blockIdx.x * 128;
    int tx = tid & 15, ty = tid >> 4;
    int arow = tid >> 1, acol4 = (tid & 1) << 2;
    int brow = tid >> 5, bcol4 = (tid & 31) << 2;
    float acc[8][8];
    #pragma unroll
    for (int i = 0; i < 8; i++)
        #pragma unroll
        for (int j = 0; j < 8; j++) acc[i][j] = 0.f;

    for (int k0 = 0; k0 < K; k0 += 8) {
        float4 av = *(const float4*)(A + (size_t)(bm + arow)*K + k0 + acol4);
        As[acol4+0][arow] = av.x; As[acol4+1][arow] = av.y;
        As[acol4+2][arow] = av.z; As[acol4+3][arow] = av.w;
        float4 bvv = *(const float4*)(Wm + (size_t)(k0 + brow)*N + bn + bcol4);
        *(float4*)&Bs[brow][bcol4] = bvv;
        __syncthreads();
        #pragma unroll
        for (int kk = 0; kk < 8; kk++) {
            float4 a0 = *(const float4*)&As[kk][ty*8];
            float4 a1 = *(const float4*)&As[kk][ty*8+4];
            float4 b0 = *(const float4*)&Bs[kk][tx*8];
            float4 b1 = *(const float4*)&Bs[kk][tx*8+4];
            float ar[8] = {a0.x,a0.y,a0.z,a0.w,a1.x,a1.y,a1.z,a1.w};
            float br[8] = {b0.x,b0.y,b0.z,b0.w,b1.x,b1.y,b1.z,b1.w};
            #pragma unroll
            for (int i = 0; i < 8; i++)
                #pragma unroll
                for (int j = 0; j < 8; j++) acc[i][j] += ar[i]*br[j];
        }
        __syncthreads();
    }
    #pragma unroll
    for (int i = 0; i < 8; i++) {
        int row = bm + ty*8 + i;
        #pragma unroll
        for (int j = 0; j < 8; j++) {
            int col = bn + tx*8 + j;
            float vv = alpha * (acc[i][j] + bias[col]);
            if (act) vv = gelu_exact(vv);
            Cout[(size_t)row*N + col] = vv;
        }
    }
}

// ---------------- sliding-window scores: per (b,h,n), 64x64 tile ----------------
__global__ __launch_bounds__(256)
void sw_scores_kernel(const float* __restrict__ q, const float* __restrict__ k,
                      const int* __restrict__ mask, float* __restrict__ scores) {
    int kt = blockIdx.x;   // 0..11 key tile
    int qt = blockIdx.y;   // 0..3 query tile
    int z  = blockIdx.z;   // (b*H+h)*NB + n
    int n  = z % NBc; int bh = z / NBc; int hh = bh % Hc; int b = bh / Hc;
    __shared__ float QsT[64][68];
    __shared__ float KsT[64][68];
    int tid = threadIdx.x;
    #pragma unroll
    for (int it = 0; it < 4; it++) {
        int idx = tid + 256*it;
        int r = idx >> 4, c4 = (idx & 15) << 2;
        int srow = n*Cc + qt*64 + r;
        float4 qv = *(const float4*)(q + ((size_t)(b*Sc + srow))*Dc + hh*64 + c4);
        QsT[c4+0][r]=qv.x; QsT[c4+1][r]=qv.y; QsT[c4+2][r]=qv.z; QsT[c4+3][r]=qv.w;
        int jg = (n-1)*Cc + kt*64 + r;
        float4 kv = make_float4(0.f,0.f,0.f,0.f);
        if (jg >= 0 && jg < Sc)
            kv = *(const float4*)(k + ((size_t)(b*Sc + jg))*Dc + hh*64 + c4);
        KsT[c4+0][r]=kv.x; KsT[c4+1][r]=kv.y; KsT[c4+2][r]=kv.z; KsT[c4+3][r]=kv.w;
    }
    __syncthreads();
    int tx = tid & 15, ty = tid >> 4;
    float acc[4][4];
    #pragma unroll
    for (int i=0;i<4;i++) for (int j=0;j<4;j++) acc[i][j]=0.f;
    #pragma unroll 16
    for (int d = 0; d < 64; d++) {
        float4 qa = *(const float4*)&QsT[d][ty*4];
        float4 kb = *(const float4*)&KsT[d][tx*4];
        float ar[4]={qa.x,qa.y,qa.z,qa.w}, br[4]={kb.x,kb.y,kb.z,kb.w};
        #pragma unroll
        for (int i=0;i<4;i++)
            #pragma unroll
            for (int j=0;j<4;j++) acc[i][j] += ar[i]*br[j];
    }
    #pragma unroll
    for (int i = 0; i < 4; i++) {
        int c = qt*64 + ty*4 + i;
        float4 outv;
        float* ov = (float*)&outv;
        #pragma unroll
        for (int j = 0; j < 4; j++) {
            int kk = kt*64 + tx*4 + j;
            int jg = (n-1)*Cc + kk;
            bool valid = (kk >= c) && (kk <= c + 2*Cc) && (jg >= 1) && (jg < Sc)
                         && (mask[b*Sc + jg] > 0);
            ov[j] = valid ? acc[i][j] : NEGF;
        }
        *(float4*)(scores + ((size_t)z*Cc + c)*W3 + kt*64 + tx*4) = outv;
    }
}

// ---------------- global-key score per (b,h,s) ----------------
__global__ void gsc_kernel(const float* __restrict__ q, const float* __restrict__ k,
                           const int* __restrict__ mask, float* __restrict__ gs) {
    int hh = blockIdx.y, b = blockIdx.z;
    int s = blockIdx.x*256 + threadIdx.x;
    __shared__ float k0s[64];
    if (threadIdx.x < 16)
        ((float4*)k0s)[threadIdx.x] = *(const float4*)(k + (size_t)(b*Sc)*Dc + hh*64 + threadIdx.x*4);
    __syncthreads();
    int m0 = mask[b*Sc];
    const float4* qr = (const float4*)(q + ((size_t)(b*Sc + s))*Dc + hh*64);
    float acc = 0.f;
    #pragma unroll
    for (int i = 0; i < 16; i++) {
        float4 a = qr[i]; float4 c = ((const float4*)k0s)[i];
        acc += a.x*c.x + a.y*c.y + a.z*c.z + a.w*c.w;
    }
    gs[((size_t)(b*Hc+hh))*Sc + s] = (m0 > 0) ? acc : NEGF;
}

// ---------------- softmax over 768 sliding + 1 global per row ----------------
__global__ void sw_softmax_kernel(float* __restrict__ scores, float* __restrict__ gs) {
    __shared__ float red[256];
    int row = blockIdx.x;                 // [0, B*H*S)
    int z = row >> 8, c = row & 255;
    int n = z % NBc, bh = z / NBc;
    size_t base = ((size_t)z*Cc + c)*W3;
    size_t gi = (size_t)bh*Sc + n*Cc + c;
    int t = threadIdx.x;
    float v0 = scores[base + t], v1 = scores[base + t + 256], v2 = scores[base + t + 512];
    float g = (t == 0) ? gs[gi] : NEGF;
    float lmax = fmaxf(fmaxf(v0, v1), fmaxf(v2, g));
    red[t] = lmax; __syncthreads();
    for (int o = 128; o > 0; o >>= 1) { if (t < o) red[t] = fmaxf(red[t], red[t+o]); __syncthreads(); }
    float M = red[0]; __syncthreads();
    float e0 = expf(v0 - M), e1 = expf(v1 - M), e2 = expf(v2 - M);
    float eg = (t == 0) ? expf(g - M) : 0.f;
    red[t] = e0 + e1 + e2 + eg; __syncthreads();
    for (int o = 128; o > 0; o >>= 1) { if (t < o) red[t] += red[t+o]; __syncthreads(); }
    float inv = 1.0f / red[0];
    scores[base + t] = e0*inv; scores[base + t + 256] = e1*inv; scores[base + t + 512] = e2*inv;
    if (t == 0) gs[gi] = eg*inv;
}

// ---------------- ctx = P @ V3 + gp*gv; per (b,h,n), 64x64 output ----------------
__global__ __launch_bounds__(256)
void sw_ctx_kernel(const float* __restrict__ probs, const float* __restrict__ gs,
                   const float* __restrict__ v, float* __restrict__ ctx) {
    int qt = blockIdx.x;
    int z  = blockIdx.y;
    int n  = z % NBc; int bh = z / NBc; int hh = bh % Hc; int b = bh / Hc;
    __shared__ float PsT[64][68];   // [kk][q]
    __shared__ float Vs [64][68];   // [kk][d]
    int tid = threadIdx.x;
    int tx = tid & 15, ty = tid >> 4;
    float acc[4][4];
    #pragma unroll
    for (int i=0;i<4;i++) for (int j=0;j<4;j++) acc[i][j]=0.f;

    for (int kc = 0; kc < W3; kc += 64) {
        #pragma unroll
        for (int it = 0; it < 4; it++) {
            int idx = tid + 256*it;
            int r = idx >> 4, c4 = (idx & 15) << 2;
            float4 pv = *(const float4*)(probs + ((size_t)z*Cc + qt*64 + r)*W3 + kc + c4);
            PsT[c4+0][r]=pv.x; PsT[c4+1][r]=pv.y; PsT[c4+2][r]=pv.z; PsT[c4+3][r]=pv.w;
            int jg = (n-1)*Cc + kc + r;
            float4 vv = make_float4(0.f,0.f,0.f,0.f);
            if (jg >= 0 && jg < Sc)
                vv = *(const float4*)(v + ((size_t)(b*Sc + jg))*Dc + hh*64 + c4);
            *(float4*)&Vs[r][c4] = vv;
        }
        __syncthreads();
        #pragma unroll 16
        for (int kk = 0; kk < 64; kk++) {
            float4 p = *(const float4*)&PsT[kk][ty*4];
            float4 w = *(const float4*)&Vs[kk][tx*4];
            float ar[4]={p.x,p.y,p.z,p.w}, br[4]={w.x,w.y,w.z,w.w};
            #pragma unroll
            for (int i=0;i<4;i++)
                #pragma unroll
                for (int j=0;j<4;j++) acc[i][j] += ar[i]*br[j];
        }
        __syncthreads();
    }
    #pragma unroll
    for (int i = 0; i < 4; i++) {
        int c = qt*64 + ty*4 + i;
        int s = n*Cc + c;
        float gp = gs[(size_t)bh*Sc + s];
        #pragma unroll
        for (int j = 0; j < 4; j++) {
            int d = tx*4 + j;
            float gvv = v[(size_t)(b*Sc)*Dc + hh*64 + d];
            ctx[((size_t)(b*Sc + s))*Dc + hh*64 + d] = acc[i][j] + gp*gvv;
        }
    }
}

// ---------------- full-attention row 0 (global token) ----------------
__global__ void attn_row0_kernel(const float* __restrict__ q0base, long q_bs,
                                 const float* __restrict__ k, const float* __restrict__ v,
                                 const int* __restrict__ mask,
                                 float* __restrict__ outbase, long out_bs) {
    int hh = blockIdx.x, b = blockIdx.y;
    __shared__ float sc[Sc];
    __shared__ float q0s[64];
    __shared__ float red[256];
    __shared__ float part[4][64];
    int tid = threadIdx.x;
    if (tid < 16)
        ((float4*)q0s)[tid] = *(const float4*)(q0base + (size_t)b*q_bs + hh*64 + tid*4);
    __syncthreads();
    float lmax = NEGF;
    for (int it = 0; it < Sc/256; it++) {
        int j = tid + 256*it;
        const float4* kr = (const float4*)(k + ((size_t)(b*Sc + j))*Dc + hh*64);
        float s = 0.f;
        #pragma unroll
        for (int d4 = 0; d4 < 16; d4++) {
            float4 kv = kr[d4]; float4 qv = ((const float4*)q0s)[d4];
            s += kv.x*qv.x + kv.y*qv.y + kv.z*qv.z + kv.w*qv.w;
        }
        if (mask[b*Sc + j] <= 0) s = NEGF;
        sc[j] = s;
        lmax = fmaxf(lmax, s);
    }
    red[tid] = lmax; __syncthreads();
    for (int o = 128; o > 0; o >>= 1) { if (tid < o) red[tid] = fmaxf(red[tid], red[tid+o]); __syncthreads(); }
    float M = red[0]; __syncthreads();
    float lsum = 0.f;
    for (int it = 0; it < Sc/256; it++) {
        int j = tid + 256*it;
        float e = expf(sc[j] - M);
        sc[j] = e; lsum += e;
    }
    red[tid] = lsum; __syncthreads();
    for (int o = 128; o > 0; o >>= 1) { if (tid < o) red[tid] += red[tid+o]; __syncthreads(); }
    float inv = 1.0f / red[0];
    __syncthreads();
    int d = tid & 63, p = tid >> 6;
    float accd = 0.f;
    for (int j = p; j < Sc; j += 4)
        accd += sc[j] * v[((size_t)(b*Sc + j))*Dc + hh*64 + d];
    part[p][d] = accd;
    __syncthreads();
    if (tid < 64) {
        float o = (part[0][tid] + part[1][tid] + part[2][tid] + part[3][tid]) * inv;
        outbase[(size_t)b*out_bs + hh*64 + tid] = o;
    }
}

// ---------------- single-row GEMM: out[b,n] = act(alpha*(x[b]·W[:,n] + bias[n])) ----------------
__global__ void row_gemm_kernel(const float* __restrict__ x, long x_bs,
                                const float* __restrict__ Wm, const float* __restrict__ bias,
                                float* __restrict__ out, long out_bs,
                                int K, int N, float alpha, int act) {
    extern __shared__ float xs[];
    int b = blockIdx.y;
    for (int i = threadIdx.x; i < K; i += 256) xs[i] = x[(size_t)b*x_bs + i];
    __syncthreads();
    int n = blockIdx.x*256 + threadIdx.x;
    if (n < N) {
        float acc = 0.f;
        for (int kk = 0; kk < K; kk++) acc += xs[kk] * Wm[(size_t)kk*N + n];
        float vv = alpha * (acc + bias[n]);
        if (act) vv = gelu_exact(vv);
        out[(size_t)b*out_bs + n] = vv;
    }
}

// =======================================================================
extern "C" void kernel_launch(void* const* d_in, const int* in_sizes, int n_in,
                              void* d_out, int out_size) {
    const int*   ids   = (const int*)d_in[0];
    const int*   mask  = (const int*)d_in[1];
    const float* etok  = (const float*)d_in[2];
    const float* epos  = (const float*)d_in[3];
    const float* eg    = (const float*)d_in[4];
    const float* ebv   = (const float*)d_in[5];
    const float* Wq    = (const float*)d_in[6];
    const float* bq    = (const float*)d_in[7];
    const float* Wk    = (const float*)d_in[8];
    const float* bk    = (const float*)d_in[9];
    const float* Wv    = (const float*)d_in[10];
    const float* bv    = (const float*)d_in[11];
    const float* Wo    = (const float*)d_in[12];
    const float* bo    = (const float*)d_in[13];
    const float* ln1g  = (const float*)d_in[14];
    const float* ln1b  = (const float*)d_in[15];
    const float* W1    = (const float*)d_in[16];
    const float* b1    = (const float*)d_in[17];
    const float* W2    = (const float*)d_in[18];
    const float* b2    = (const float*)d_in[19];
    const float* ln2g  = (const float*)d_in[20];
    const float* ln2b  = (const float*)d_in[21];
    const float* clsW  = (const float*)d_in[22];
    const float* clsb  = (const float*)d_in[23];
    float* out = (float*)d_out;

    float *h,*q,*k,*v,*ctx,*att,*mid,*sc,*gs,*q0,*o0,*a0,*h0,*f0,*m0;
    cudaGetSymbolAddress((void**)&h,   g_h);
    cudaGetSymbolAddress((void**)&q,   g_q);
    cudaGetSymbolAddress((void**)&k,   g_k);
    cudaGetSymbolAddress((void**)&v,   g_v);
    cudaGetSymbolAddress((void**)&ctx, g_ctx);
    cudaGetSymbolAddress((void**)&att, g_att);
    cudaGetSymbolAddress((void**)&mid, g_mid);
    cudaGetSymbolAddress((void**)&sc,  g_sc);
    cudaGetSymbolAddress((void**)&gs,  g_gs);
    cudaGetSymbolAddress((void**)&q0,  g_q0);
    cudaGetSymbolAddress((void**)&o0,  g_o0);
    cudaGetSymbolAddress((void**)&a0,  g_a0);
    cudaGetSymbolAddress((void**)&h0,  g_h0);
    cudaGetSymbolAddress((void**)&f0,  g_f0);
    cudaGetSymbolAddress((void**)&m0,  g_m0);

    const int M = Bc*Sc;                 // 8192
    dim3 gD(Dc/128, M/128);              // (6, 64)
    dim3 gF(Fc/128, M/128);              // (24, 64)

    // ---- embeddings ----
    embed_gather<<<(Bc*Sc*Dc + 255)/256, 256>>>(ids, etok, epos, ctx);
    ln_kernel<<<M, 256>>>(ctx, Dc, nullptr, 0, eg, ebv, h, Dc);

    // ---- layer 0 (full) ----
    gemm_kernel<<<gD, 256>>>(h, Wq, bq, q, M, Dc, Dc, 0.125f, 0);
    gemm_kernel<<<gD, 256>>>(h, Wk, bk, k, M, Dc, Dc, 1.0f, 0);
    gemm_kernel<<<gD, 256>>>(h, Wv, bv, v, M, Dc, Dc, 1.0f, 0);
    sw_scores_kernel<<<dim3(12, 4, Bc*Hc*NBc), 256>>>(q, k, mask, sc);
    gsc_kernel<<<dim3(Sc/256, Hc, Bc), 256>>>(q, k, mask, gs);
    sw_softmax_kernel<<<Bc*Hc*Sc, 256>>>(sc, gs);
    sw_ctx_kernel<<<dim3(4, Bc*Hc*NBc), 256>>>(sc, gs, v, ctx);
    attn_row0_kernel<<<dim3(Hc, Bc), 256>>>(q, (long)Sc*Dc, k, v, mask, ctx, (long)Sc*Dc);
    gemm_kernel<<<gD, 256>>>(ctx, Wo, bo, att, M, Dc, Dc, 1.0f, 0);
    ln_kernel<<<M, 256>>>(h, Dc, att, Dc, ln1g, ln1b, h, Dc);
    gemm_kernel<<<gF, 256>>>(h, W1, b1, mid, M, Fc, Dc, 1.0f, 1);
    gemm_kernel<<<gD, 256>>>(mid, W2, b2, att, M, Dc, Fc, 1.0f, 0);
    ln_kernel<<<M, 256>>>(h, Dc, att, Dc, ln2g, ln2b, h, Dc);

    // ---- layer 1 (pruned: only position 0 survives to the classifier) ----
    const float* Wq1 = Wq + (size_t)Dc*Dc; const float* bq1 = bq + Dc;
    const float* Wk1 = Wk + (size_t)Dc*Dc; const float* bk1 = bk + Dc;
    const float* Wv1 = Wv + (size_t)Dc*Dc; const float* bv1 = bv + Dc;
    const float* Wo1 = Wo + (size_t)Dc*Dc; const float* bo1 = bo + Dc;
    const float* W11 = W1 + (size_t)Dc*Fc; const float* b11 = b1 + Fc;
    const float* W21 = W2 + (size_t)Fc*Dc; const float* b21 = b2 + Dc;

    gemm_kernel<<<gD, 256>>>(h, Wk1, bk1, k, M, Dc, Dc, 1.0f, 0);
    gemm_kernel<<<gD, 256>>>(h, Wv1, bv1, v, M, Dc, Dc, 1.0f, 0);
    row_gemm_kernel<<<dim3(Dc/256, Bc), 256, Dc*sizeof(float)>>>(
        h, (long)Sc*Dc, Wq1, bq1, q0, Dc, Dc, Dc, 0.125f, 0);
    attn_row0_kernel<<<dim3(Hc, Bc), 256>>>(q0, (long)Dc, k, v, mask, o0, (long)Dc);
    row_gemm_kernel<<<dim3(Dc/256, Bc), 256, Dc*sizeof(float)>>>(
        o0, (long)Dc, Wo1, bo1, a0, Dc, Dc, Dc, 1.0f, 0);
    ln_kernel<<<Bc, 256>>>(h, (long)Sc*Dc, a0, Dc, ln1g + Dc, ln1b + Dc, h0, Dc);
    row_gemm_kernel<<<dim3(Fc/256, Bc), 256, Dc*sizeof(float)>>>(
        h0, (long)Dc, W11, b11, m0, Fc, Dc, Fc, 1.0f, 1);
    row_gemm_kernel<<<dim3(Dc/256, Bc), 256, Fc*sizeof(float)>>>(
        m0, (long)Fc, W21, b21, f0, Dc, Fc, Dc, 1.0f, 0);
    ln_kernel<<<Bc, 256>>>(h0, Dc, f0, Dc, ln2g + Dc, ln2b + Dc, h0, Dc);
    row_gemm_kernel<<<dim3(1, Bc), 256, Dc*sizeof(float)>>>(
        h0, (long)Dc, clsW, clsb, out, 3, Dc, 3, 1.0f, 0);
}

// round 2
// speedup vs baseline: 2.1078x; 2.1078x over previous
#include <cuda_runtime.h>
#include <math.h>
#include <stdint.h>

#define Bc 2
#define Sc 4096
#define Dc 768
#define Hc 12
#define DHc 64
#define Lc 2
#define Fc 3072
#define Cc 256
#define NBc 16
#define W3 (3*Cc)
#define NEGF (-1000000000.0f)

// ---------------- scratch (device globals; no allocation allowed) ----------------
__device__ float g_h  [(size_t)Bc*Sc*Dc];
__device__ float g_q  [(size_t)Bc*Sc*Dc];
__device__ float g_k  [(size_t)Bc*Sc*Dc];
__device__ float g_v  [(size_t)Bc*Sc*Dc];
__device__ float g_ctx[(size_t)Bc*Sc*Dc];
__device__ float g_att[(size_t)Bc*Sc*Dc];
__device__ float g_mid[(size_t)Bc*Sc*Fc];
__device__ float g_sc [(size_t)Bc*Hc*NBc*Cc*W3];   // sliding scores/probs
__device__ float g_gs [(size_t)Bc*Hc*Sc];          // global-key score/prob
__device__ float g_q0 [Bc*Dc];
__device__ float g_o0 [Bc*Dc];
__device__ float g_a0 [Bc*Dc];
__device__ float g_h0 [Bc*Dc];
__device__ float g_f0 [Bc*Dc];
__device__ float g_m0 [Bc*Fc];

__device__ __forceinline__ float gelu_exact(float x) {
    return 0.5f * x * (1.0f + erff(x * 0.70710678118654752f));
}

__device__ __forceinline__ uint32_t f2tf32(float x) {
    uint32_t r;
    asm("cvt.rna.tf32.f32 %0, %1;" : "=r"(r) : "f"(x));
    return r;
}

__device__ __forceinline__ void mma_tf32(float* c,
    uint32_t a0, uint32_t a1, uint32_t a2, uint32_t a3,
    uint32_t b0, uint32_t b1) {
    asm volatile(
        "mma.sync.aligned.m16n8k8.row.col.f32.tf32.tf32.f32 "
        "{%0,%1,%2,%3}, {%4,%5,%6,%7}, {%8,%9}, {%0,%1,%2,%3};"
        : "+f"(c[0]), "+f"(c[1]), "+f"(c[2]), "+f"(c[3])
        : "r"(a0), "r"(a1), "r"(a2), "r"(a3), "r"(b0), "r"(b1));
}

// ---------------- embedding gather ----------------
__global__ void embed_gather(const int* __restrict__ ids, const float* __restrict__ tok,
                             const float* __restrict__ pos, float* __restrict__ out) {
    long i = (long)blockIdx.x * 256 + threadIdx.x;
    if (i >= (long)Bc*Sc*Dc) return;
    long bs = i / Dc; int d = (int)(i % Dc); int s = (int)(bs % Sc);
    out[i] = tok[(size_t)ids[bs]*Dc + d] + pos[(size_t)s*Dc + d];
}

// ---------------- LayerNorm (+optional residual); one block per row, D=768 ----------------
__global__ void ln_kernel(const float* __restrict__ x, long xs,
                          const float* __restrict__ res, long rs,
                          const float* __restrict__ g, const float* __restrict__ bb,
                          float* __restrict__ out, long os) {
    __shared__ float red[256];
    int row = blockIdx.x, t = threadIdx.x;
    const float* xr = x + (size_t)row * xs;
    float v0 = xr[t], v1 = xr[t+256], v2 = xr[t+512];
    if (res) {
        const float* rr = res + (size_t)row * rs;
        v0 += rr[t]; v1 += rr[t+256]; v2 += rr[t+512];
    }
    float s = v0 + v1 + v2;
    red[t] = s; __syncthreads();
    for (int o = 128; o > 0; o >>= 1) { if (t < o) red[t] += red[t+o]; __syncthreads(); }
    float mean = red[0] * (1.0f/768.0f); __syncthreads();
    float d0 = v0-mean, d1 = v1-mean, d2 = v2-mean;
    red[t] = d0*d0 + d1*d1 + d2*d2; __syncthreads();
    for (int o = 128; o > 0; o >>= 1) { if (t < o) red[t] += red[t+o]; __syncthreads(); }
    float rstd = rsqrtf(red[0] * (1.0f/768.0f) + 1e-5f);
    float* orow = out + (size_t)row * os;
    orow[t]     = d0*rstd*g[t]     + bb[t];
    orow[t+256] = d1*rstd*g[t+256] + bb[t+256];
    orow[t+512] = d2*rstd*g[t+512] + bb[t+512];
}

// ---------------- tf32 tensor-core GEMM: C = act(alpha*(A@W + bias)) ----------------
// 128x128x32 tile, 256 threads (8 warps, 2x4), warp tile 64x32 via m16n8k8.
__global__ __launch_bounds__(256, 2)
void gemm_tc_kernel(const float* __restrict__ A, const float* __restrict__ Wm,
                    const float* __restrict__ bias, float* __restrict__ Cout,
                    int M, int N, int K, float alpha, int act) {
    __shared__ uint32_t As[128][40];   // [m][k], stride 40 -> frag LDS conflict-free
    __shared__ uint32_t Bs[32][136];   // [k][n], stride 136 -> frag LDS conflict-free

    int t = threadIdx.x;
    int lane = t & 31, warp = t >> 5;
    int gid = lane >> 2, tig = lane & 3;
    int wm = (warp >> 2) * 64;    // 0 or 64
    int wn = (warp & 3) * 32;     // 0..96
    int bm = blockIdx.y * 128, bn = blockIdx.x * 128;

    float acc[4][4][4];
    #pragma unroll
    for (int i = 0; i < 4; i++)
        #pragma unroll
        for (int j = 0; j < 4; j++)
            #pragma unroll
            for (int r = 0; r < 4; r++) acc[i][j][r] = 0.f;

    int arow = t >> 3;          // 0..31
    int acol = (t & 7) * 4;     // 0..28
    int brow = t >> 5;          // 0..7
    int bcol = (t & 31) * 4;    // 0..124

    float4 pa[4], pb[4];
    // prefetch tile 0
    #pragma unroll
    for (int r = 0; r < 4; r++)
        pa[r] = *(const float4*)(A + (size_t)(bm + arow + r*32)*K + acol);
    #pragma unroll
    for (int r = 0; r < 4; r++)
        pb[r] = *(const float4*)(Wm + (size_t)(brow + r*8)*N + bn + bcol);

    int KT = K >> 5;
    for (int kt = 0; kt < KT; kt++) {
        // store prefetched tile to smem (tf32-rounded)
        #pragma unroll
        for (int r = 0; r < 4; r++) {
            As[arow + r*32][acol+0] = f2tf32(pa[r].x);
            As[arow + r*32][acol+1] = f2tf32(pa[r].y);
            As[arow + r*32][acol+2] = f2tf32(pa[r].z);
            As[arow + r*32][acol+3] = f2tf32(pa[r].w);
            uint4 bw;
            bw.x = f2tf32(pb[r].x); bw.y = f2tf32(pb[r].y);
            bw.z = f2tf32(pb[r].z); bw.w = f2tf32(pb[r].w);
            *(uint4*)&Bs[brow + r*8][bcol] = bw;
        }
        __syncthreads();
        if (kt + 1 < KT) {
            int k0 = (kt + 1) * 32;
            #pragma unroll
            for (int r = 0; r < 4; r++)
                pa[r] = *(const float4*)(A + (size_t)(bm + arow + r*32)*K + k0 + acol);
            #pragma unroll
            for (int r = 0; r < 4; r++)
                pb[r] = *(const float4*)(Wm + (size_t)(k0 + brow + r*8)*N + bn + bcol);
        }
        #pragma unroll
        for (int ks = 0; ks < 4; ks++) {
            int kk = ks * 8;
            uint32_t af[4][4], bf[4][2];
            #pragma unroll
            for (int mi = 0; mi < 4; mi++) {
                int m = wm + mi*16 + gid;
                af[mi][0] = As[m    ][kk + tig];
                af[mi][1] = As[m + 8][kk + tig];
                af[mi][2] = As[m    ][kk + tig + 4];
                af[mi][3] = As[m + 8][kk + tig + 4];
            }
            #pragma unroll
            for (int ni = 0; ni < 4; ni++) {
                int n = wn + ni*8 + gid;
                bf[ni][0] = Bs[kk + tig    ][n];
                bf[ni][1] = Bs[kk + tig + 4][n];
            }
            #pragma unroll
            for (int mi = 0; mi < 4; mi++)
                #pragma unroll
                for (int ni = 0; ni < 4; ni++)
                    mma_tf32(acc[mi][ni], af[mi][0], af[mi][1], af[mi][2], af[mi][3],
                             bf[ni][0], bf[ni][1]);
        }
        __syncthreads();
    }

    // epilogue
    #pragma unroll
    for (int mi = 0; mi < 4; mi++) {
        #pragma unroll
        for (int ni = 0; ni < 4; ni++) {
            int col = bn + wn + ni*8 + 2*tig;
            float b0v = bias[col], b1v = bias[col+1];
            #pragma unroll
            for (int half = 0; half < 2; half++) {
                int row = bm + wm + mi*16 + gid + half*8;
                float v0 = alpha * (acc[mi][ni][half*2+0] + b0v);
                float v1 = alpha * (acc[mi][ni][half*2+1] + b1v);
                if (act) { v0 = gelu_exact(v0); v1 = gelu_exact(v1); }
                float2 o; o.x = v0; o.y = v1;
                *(float2*)(Cout + (size_t)row*N + col) = o;
            }
        }
    }
}

// ---------------- sliding-window scores (tf32 mma): per (kt,qt,z), 64x64 tile ----------------
__global__ __launch_bounds__(128)
void sw_scores_kernel(const float* __restrict__ q, const float* __restrict__ k,
                      const int* __restrict__ mask, float* __restrict__ scores) {
    int kt = blockIdx.x;   // 0..11 key tile
    int qt = blockIdx.y;   // 0..3 query tile
    int z  = blockIdx.z;   // (b*H+h)*NB + n
    int n  = z % NBc; int bh = z / NBc; int hh = bh % Hc; int b = bh / Hc;
    __shared__ uint32_t Qs[64][72];  // [c][d]
    __shared__ uint32_t Ks[64][72];  // [kk][d]
    int t = threadIdx.x;
    int lane = t & 31, warp = t >> 5;
    int gid = lane >> 2, tig = lane & 3;
    int wm = (warp >> 1) * 32, wn = (warp & 1) * 32;

    #pragma unroll
    for (int r = 0; r < 8; r++) {
        int row = r*8 + (t >> 4);
        int c4 = (t & 15) * 4;
        float4 qv = *(const float4*)(q + ((size_t)(b*Sc + n*Cc + qt*64 + row))*Dc + hh*64 + c4);
        Qs[row][c4+0] = f2tf32(qv.x); Qs[row][c4+1] = f2tf32(qv.y);
        Qs[row][c4+2] = f2tf32(qv.z); Qs[row][c4+3] = f2tf32(qv.w);
        int jg = (n-1)*Cc + kt*64 + row;
        float4 kv = make_float4(0.f,0.f,0.f,0.f);
        if (jg >= 0 && jg < Sc)
            kv = *(const float4*)(k + ((size_t)(b*Sc + jg))*Dc + hh*64 + c4);
        Ks[row][c4+0] = f2tf32(kv.x); Ks[row][c4+1] = f2tf32(kv.y);
        Ks[row][c4+2] = f2tf32(kv.z); Ks[row][c4+3] = f2tf32(kv.w);
    }
    __syncthreads();

    float acc[2][4][4];
    #pragma unroll
    for (int i=0;i<2;i++) for (int j=0;j<4;j++) for (int r=0;r<4;r++) acc[i][j][r]=0.f;

    #pragma unroll
    for (int ks = 0; ks < 8; ks++) {
        int kk = ks * 8;
        uint32_t af[2][4], bf[4][2];
        #pragma unroll
        for (int mi = 0; mi < 2; mi++) {
            int m = wm + mi*16 + gid;
            af[mi][0] = Qs[m    ][kk + tig];
            af[mi][1] = Qs[m + 8][kk + tig];
            af[mi][2] = Qs[m    ][kk + tig + 4];
            af[mi][3] = Qs[m + 8][kk + tig + 4];
        }
        #pragma unroll
        for (int ni = 0; ni < 4; ni++) {
            int nn = wn + ni*8 + gid;
            bf[ni][0] = Ks[nn][kk + tig];
            bf[ni][1] = Ks[nn][kk + tig + 4];
        }
        #pragma unroll
        for (int mi = 0; mi < 2; mi++)
            #pragma unroll
            for (int ni = 0; ni < 4; ni++)
                mma_tf32(acc[mi][ni], af[mi][0], af[mi][1], af[mi][2], af[mi][3],
                         bf[ni][0], bf[ni][1]);
    }

    #pragma unroll
    for (int mi = 0; mi < 2; mi++) {
        #pragma unroll
        for (int ni = 0; ni < 4; ni++) {
            #pragma unroll
            for (int half = 0; half < 2; half++) {
                int c = qt*64 + wm + mi*16 + gid + half*8;
                #pragma unroll
                for (int e = 0; e < 2; e++) {
                    int kkc = kt*64 + wn + ni*8 + 2*tig + e;
                    int jg = (n-1)*Cc + kkc;
                    bool valid = (kkc >= c) && (kkc <= c + 2*Cc) && (jg >= 1) && (jg < Sc)
                                 && (mask[b*Sc + jg] > 0);
                    scores[((size_t)z*Cc + c)*W3 + kkc] =
                        valid ? acc[mi][ni][half*2+e] : NEGF;
                }
            }
        }
    }
}

// ---------------- global-key score per (b,h,s) ----------------
__global__ void gsc_kernel(const float* __restrict__ q, const float* __restrict__ k,
                           const int* __restrict__ mask, float* __restrict__ gs) {
    int hh = blockIdx.y, b = blockIdx.z;
    int s = blockIdx.x*256 + threadIdx.x;
    __shared__ float k0s[64];
    if (threadIdx.x < 16)
        ((float4*)k0s)[threadIdx.x] = *(const float4*)(k + (size_t)(b*Sc)*Dc + hh*64 + threadIdx.x*4);
    __syncthreads();
    int m0 = mask[b*Sc];
    const float4* qr = (const float4*)(q + ((size_t)(b*Sc + s))*Dc + hh*64);
    float acc = 0.f;
    #pragma unroll
    for (int i = 0; i < 16; i++) {
        float4 a = qr[i]; float4 c = ((const float4*)k0s)[i];
        acc += a.x*c.x + a.y*c.y + a.z*c.z + a.w*c.w;
    }
    gs[((size_t)(b*Hc+hh))*Sc + s] = (m0 > 0) ? acc : NEGF;
}

// ---------------- softmax over 768 sliding + 1 global per row ----------------
__global__ void sw_softmax_kernel(float* __restrict__ scores, float* __restrict__ gs) {
    __shared__ float red[256];
    int row = blockIdx.x;                 // [0, B*H*S)
    int z = row >> 8, c = row & 255;
    int n = z % NBc, bh = z / NBc;
    size_t base = ((size_t)z*Cc + c)*W3;
    size_t gi = (size_t)bh*Sc + n*Cc + c;
    int t = threadIdx.x;
    float v0 = scores[base + t], v1 = scores[base + t + 256], v2 = scores[base + t + 512];
    float g = (t == 0) ? gs[gi] : NEGF;
    float lmax = fmaxf(fmaxf(v0, v1), fmaxf(v2, g));
    red[t] = lmax; __syncthreads();
    for (int o = 128; o > 0; o >>= 1) { if (t < o) red[t] = fmaxf(red[t], red[t+o]); __syncthreads(); }
    float M = red[0]; __syncthreads();
    float e0 = expf(v0 - M), e1 = expf(v1 - M), e2 = expf(v2 - M);
    float eg = (t == 0) ? expf(g - M) : 0.f;
    red[t] = e0 + e1 + e2 + eg; __syncthreads();
    for (int o = 128; o > 0; o >>= 1) { if (t < o) red[t] += red[t+o]; __syncthreads(); }
    float inv = 1.0f / red[0];
    scores[base + t] = e0*inv; scores[base + t + 256] = e1*inv; scores[base + t + 512] = e2*inv;
    if (t == 0) gs[gi] = eg*inv;
}

// ---------------- ctx = P @ V3 + gp*gv (tf32 mma); per (qt,z), 64x64 output ----------------
__global__ __launch_bounds__(128)
void sw_ctx_kernel(const float* __restrict__ probs, const float* __restrict__ gs,
                   const float* __restrict__ v, float* __restrict__ ctx) {
    int qt = blockIdx.x;
    int z  = blockIdx.y;
    int n  = z % NBc; int bh = z / NBc; int hh = bh % Hc; int b = bh / Hc;
    __shared__ uint32_t Ps[64][72];   // [c][kk]
    __shared__ uint32_t Vs[64][72];   // [kk][d]
    int t = threadIdx.x;
    int lane = t & 31, warp = t >> 5;
    int gid = lane >> 2, tig = lane & 3;
    int wm = (warp >> 1) * 32, wn = (warp & 1) * 32;

    float acc[2][4][4];
    #pragma unroll
    for (int i=0;i<2;i++) for (int j=0;j<4;j++) for (int r=0;r<4;r++) acc[i][j][r]=0.f;

    for (int kc = 0; kc < W3; kc += 64) {
        #pragma unroll
        for (int r = 0; r < 8; r++) {
            int row = r*8 + (t >> 4);
            int c4 = (t & 15) * 4;
            float4 pv = *(const float4*)(probs + ((size_t)z*Cc + qt*64 + row)*W3 + kc + c4);
            Ps[row][c4+0] = f2tf32(pv.x); Ps[row][c4+1] = f2tf32(pv.y);
            Ps[row][c4+2] = f2tf32(pv.z); Ps[row][c4+3] = f2tf32(pv.w);
            int jg = (n-1)*Cc + kc + row;
            float4 vv = make_float4(0.f,0.f,0.f,0.f);
            if (jg >= 0 && jg < Sc)
                vv = *(const float4*)(v + ((size_t)(b*Sc + jg))*Dc + hh*64 + c4);
            Vs[row][c4+0] = f2tf32(vv.x); Vs[row][c4+1] = f2tf32(vv.y);
            Vs[row][c4+2] = f2tf32(vv.z); Vs[row][c4+3] = f2tf32(vv.w);
        }
        __syncthreads();
        #pragma unroll
        for (int ks = 0; ks < 8; ks++) {
            int kk = ks * 8;
            uint32_t af[2][4], bf[4][2];
            #pragma unroll
            for (int mi = 0; mi < 2; mi++) {
                int m = wm + mi*16 + gid;
                af[mi][0] = Ps[m    ][kk + tig];
                af[mi][1] = Ps[m + 8][kk + tig];
                af[mi][2] = Ps[m    ][kk + tig + 4];
                af[mi][3] = Ps[m + 8][kk + tig + 4];
            }
            #pragma unroll
            for (int ni = 0; ni < 4; ni++) {
                int nn = wn + ni*8 + gid;
                bf[ni][0] = Vs[kk + tig    ][nn];
                bf[ni][1] = Vs[kk + tig + 4][nn];
            }
            #pragma unroll
            for (int mi = 0; mi < 2; mi++)
                #pragma unroll
                for (int ni = 0; ni < 4; ni++)
                    mma_tf32(acc[mi][ni], af[mi][0], af[mi][1], af[mi][2], af[mi][3],
                             bf[ni][0], bf[ni][1]);
        }
        __syncthreads();
    }

    #pragma unroll
    for (int mi = 0; mi < 2; mi++) {
        #pragma unroll
        for (int half = 0; half < 2; half++) {
            int s = n*Cc + qt*64 + wm + mi*16 + gid + half*8;
            float gp = gs[(size_t)bh*Sc + s];
            #pragma unroll
            for (int ni = 0; ni < 4; ni++) {
                #pragma unroll
                for (int e = 0; e < 2; e++) {
                    int d = wn + ni*8 + 2*tig + e;
                    float gvv = v[(size_t)(b*Sc)*Dc + hh*64 + d];
                    ctx[((size_t)(b*Sc + s))*Dc + hh*64 + d] =
                        acc[mi][ni][half*2+e] + gp*gvv;
                }
            }
        }
    }
}

// ---------------- full-attention row 0 (global token) ----------------
__global__ void attn_row0_kernel(const float* __restrict__ q0base, long q_bs,
                                 const float* __restrict__ k, const float* __restrict__ v,
                                 const int* __restrict__ mask,
                                 float* __restrict__ outbase, long out_bs) {
    int hh = blockIdx.x, b = blockIdx.y;
    __shared__ float sc[Sc];
    __shared__ float q0s[64];
    __shared__ float red[256];
    __shared__ float part[4][64];
    int tid = threadIdx.x;
    if (tid < 16)
        ((float4*)q0s)[tid] = *(const float4*)(q0base + (size_t)b*q_bs + hh*64 + tid*4);
    __syncthreads();
    float lmax = NEGF;
    for (int it = 0; it < Sc/256; it++) {
        int j = tid + 256*it;
        const float4* kr = (const float4*)(k + ((size_t)(b*Sc + j))*Dc + hh*64);
        float s = 0.f;
        #pragma unroll
        for (int d4 = 0; d4 < 16; d4++) {
            float4 kv = kr[d4]; float4 qv = ((const float4*)q0s)[d4];
            s += kv.x*qv.x + kv.y*qv.y + kv.z*qv.z + kv.w*qv.w;
        }
        if (mask[b*Sc + j] <= 0) s = NEGF;
        sc[j] = s;
        lmax = fmaxf(lmax, s);
    }
    red[tid] = lmax; __syncthreads();
    for (int o = 128; o > 0; o >>= 1) { if (tid < o) red[tid] = fmaxf(red[tid], red[tid+o]); __syncthreads(); }
    float M = red[0]; __syncthreads();
    float lsum = 0.f;
    for (int it = 0; it < Sc/256; it++) {
        int j = tid + 256*it;
        float e = expf(sc[j] - M);
        sc[j] = e; lsum += e;
    }
    red[tid] = lsum; __syncthreads();
    for (int o = 128; o > 0; o >>= 1) { if (tid < o) red[tid] += red[tid+o]; __syncthreads(); }
    float inv = 1.0f / red[0];
    __syncthreads();
    int d = tid & 63, p = tid >> 6;
    float accd = 0.f;
    for (int j = p; j < Sc; j += 4)
        accd += sc[j] * v[((size_t)(b*Sc + j))*Dc + hh*64 + d];
    part[p][d] = accd;
    __syncthreads();
    if (tid < 64) {
        float o = (part[0][tid] + part[1][tid] + part[2][tid] + part[3][tid]) * inv;
        outbase[(size_t)b*out_bs + hh*64 + tid] = o;
    }
}

// ---------------- single-row GEMM ----------------
__global__ void row_gemm_kernel(const float* __restrict__ x, long x_bs,
                                const float* __restrict__ Wm, const float* __restrict__ bias,
                                float* __restrict__ out, long out_bs,
                                int K, int N, float alpha, int act) {
    extern __shared__ float xs[];
    int b = blockIdx.y;
    for (int i = threadIdx.x; i < K; i += 256) xs[i] = x[(size_t)b*x_bs + i];
    __syncthreads();
    int n = blockIdx.x*256 + threadIdx.x;
    if (n < N) {
        float acc = 0.f;
        for (int kk = 0; kk < K; kk++) acc += xs[kk] * Wm[(size_t)kk*N + n];
        float vv = alpha * (acc + bias[n]);
        if (act) vv = gelu_exact(vv);
        out[(size_t)b*out_bs + n] = vv;
    }
}

// =======================================================================
extern "C" void kernel_launch(void* const* d_in, const int* in_sizes, int n_in,
                              void* d_out, int out_size) {
    const int*   ids   = (const int*)d_in[0];
    const int*   mask  = (const int*)d_in[1];
    const float* etok  = (const float*)d_in[2];
    const float* epos  = (const float*)d_in[3];
    const float* eg    = (const float*)d_in[4];
    const float* ebv   = (const float*)d_in[5];
    const float* Wq    = (const float*)d_in[6];
    const float* bq    = (const float*)d_in[7];
    const float* Wk    = (const float*)d_in[8];
    const float* bk    = (const float*)d_in[9];
    const float* Wv    = (const float*)d_in[10];
    const float* bv    = (const float*)d_in[11];
    const float* Wo    = (const float*)d_in[12];
    const float* bo    = (const float*)d_in[13];
    const float* ln1g  = (const float*)d_in[14];
    const float* ln1b  = (const float*)d_in[15];
    const float* W1    = (const float*)d_in[16];
    const float* b1    = (const float*)d_in[17];
    const float* W2    = (const float*)d_in[18];
    const float* b2    = (const float*)d_in[19];
    const float* ln2g  = (const float*)d_in[20];
    const float* ln2b  = (const float*)d_in[21];
    const float* clsW  = (const float*)d_in[22];
    const float* clsb  = (const float*)d_in[23];
    float* out = (float*)d_out;

    float *h,*q,*k,*v,*ctx,*att,*mid,*sc,*gs,*q0,*o0,*a0,*h0,*f0,*m0;
    cudaGetSymbolAddress((void**)&h,   g_h);
    cudaGetSymbolAddress((void**)&q,   g_q);
    cudaGetSymbolAddress((void**)&k,   g_k);
    cudaGetSymbolAddress((void**)&v,   g_v);
    cudaGetSymbolAddress((void**)&ctx, g_ctx);
    cudaGetSymbolAddress((void**)&att, g_att);
    cudaGetSymbolAddress((void**)&mid, g_mid);
    cudaGetSymbolAddress((void**)&sc,  g_sc);
    cudaGetSymbolAddress((void**)&gs,  g_gs);
    cudaGetSymbolAddress((void**)&q0,  g_q0);
    cudaGetSymbolAddress((void**)&o0,  g_o0);
    cudaGetSymbolAddress((void**)&a0,  g_a0);
    cudaGetSymbolAddress((void**)&h0,  g_h0);
    cudaGetSymbolAddress((void**)&f0,  g_f0);
    cudaGetSymbolAddress((void**)&m0,  g_m0);

    const int M = Bc*Sc;                 // 8192
    dim3 gD(Dc/128, M/128);              // (6, 64)
    dim3 gF(Fc/128, M/128);              // (24, 64)

    // ---- embeddings ----
    embed_gather<<<(Bc*Sc*Dc + 255)/256, 256>>>(ids, etok, epos, ctx);
    ln_kernel<<<M, 256>>>(ctx, Dc, nullptr, 0, eg, ebv, h, Dc);

    // ---- layer 0 (full) ----
    gemm_tc_kernel<<<gD, 256>>>(h, Wq, bq, q, M, Dc, Dc, 0.125f, 0);
    gemm_tc_kernel<<<gD, 256>>>(h, Wk, bk, k, M, Dc, Dc, 1.0f, 0);
    gemm_tc_kernel<<<gD, 256>>>(h, Wv, bv, v, M, Dc, Dc, 1.0f, 0);
    sw_scores_kernel<<<dim3(12, 4, Bc*Hc*NBc), 128>>>(q, k, mask, sc);
    gsc_kernel<<<dim3(Sc/256, Hc, Bc), 256>>>(q, k, mask, gs);
    sw_softmax_kernel<<<Bc*Hc*Sc, 256>>>(sc, gs);
    sw_ctx_kernel<<<dim3(4, Bc*Hc*NBc), 128>>>(sc, gs, v, ctx);
    attn_row0_kernel<<<dim3(Hc, Bc), 256>>>(q, (long)Sc*Dc, k, v, mask, ctx, (long)Sc*Dc);
    gemm_tc_kernel<<<gD, 256>>>(ctx, Wo, bo, att, M, Dc, Dc, 1.0f, 0);
    ln_kernel<<<M, 256>>>(h, Dc, att, Dc, ln1g, ln1b, h, Dc);
    gemm_tc_kernel<<<gF, 256>>>(h, W1, b1, mid, M, Fc, Dc, 1.0f, 1);
    gemm_tc_kernel<<<gD, 256>>>(mid, W2, b2, att, M, Dc, Fc, 1.0f, 0);
    ln_kernel<<<M, 256>>>(h, Dc, att, Dc, ln2g, ln2b, h, Dc);

    // ---- layer 1 (pruned: only position 0 survives to the classifier) ----
    const float* Wq1 = Wq + (size_t)Dc*Dc; const float* bq1 = bq + Dc;
    const float* Wk1 = Wk + (size_t)Dc*Dc; const float* bk1 = bk + Dc;
    const float* Wv1 = Wv + (size_t)Dc*Dc; const float* bv1 = bv + Dc;
    const float* Wo1 = Wo + (size_t)Dc*Dc; const float* bo1 = bo + Dc;
    const float* W11 = W1 + (size_t)Dc*Fc; const float* b11 = b1 + Fc;
    const float* W21 = W2 + (size_t)Fc*Dc; const float* b21 = b2 + Dc;

    gemm_tc_kernel<<<gD, 256>>>(h, Wk1, bk1, k, M, Dc, Dc, 1.0f, 0);
    gemm_tc_kernel<<<gD, 256>>>(h, Wv1, bv1, v, M, Dc, Dc, 1.0f, 0);
    row_gemm_kernel<<<dim3(Dc/256, Bc), 256, Dc*sizeof(float)>>>(
        h, (long)Sc*Dc, Wq1, bq1, q0, Dc, Dc, Dc, 0.125f, 0);
    attn_row0_kernel<<<dim3(Hc, Bc), 256>>>(q0, (long)Dc, k, v, mask, o0, (long)Dc);
    row_gemm_kernel<<<dim3(Dc/256, Bc), 256, Dc*sizeof(float)>>>(
        o0, (long)Dc, Wo1, bo1, a0, Dc, Dc, Dc, 1.0f, 0);
    ln_kernel<<<Bc, 256>>>(h, (long)Sc*Dc, a0, Dc, ln1g + Dc, ln1b + Dc, h0, Dc);
    row_gemm_kernel<<<dim3(Fc/256, Bc), 256, Dc*sizeof(float)>>>(
        h0, (long)Dc, W11, b11, m0, Fc, Dc, Fc, 1.0f, 1);
    row_gemm_kernel<<<dim3(Dc/256, Bc), 256, Fc*sizeof(float)>>>(
        m0, (long)Fc, W21, b21, f0, Dc, Fc, Dc, 1.0f, 0);
    ln_kernel<<<Bc, 256>>>(h0, Dc, f0, Dc, ln2g + Dc, ln2b + Dc, h0, Dc);
    row_gemm_kernel<<<dim3(1, Bc), 256, Dc*sizeof(float)>>>(
        h0, (long)Dc, clsW, clsb, out, 3, Dc, 3, 1.0f, 0);
}

// round 3
// speedup vs baseline: 2.5662x; 1.2175x over previous
#include <cuda_runtime.h>
#include <math.h>
#include <stdint.h>

#define Bc 2
#define Sc 4096
#define Dc 768
#define Hc 12
#define DHc 64
#define Lc 2
#define Fc 3072
#define Cc 256
#define NBc 16
#define W3 (3*Cc)
#define NEGF (-1000000000.0f)

// ---------------- scratch (device globals; no allocation allowed) ----------------
__device__ float g_h  [(size_t)Bc*Sc*Dc];
__device__ float g_q  [(size_t)Bc*Sc*Dc];
__device__ float g_k  [(size_t)Bc*Sc*Dc];
__device__ float g_v  [(size_t)Bc*Sc*Dc];
__device__ float g_ctx[(size_t)Bc*Sc*Dc];
__device__ float g_att[(size_t)Bc*Sc*Dc];
__device__ float g_mid[(size_t)Bc*Sc*Fc];
__device__ float g_q0 [Bc*Dc];
__device__ float g_o0 [Bc*Dc];
__device__ float g_a0 [Bc*Dc];
__device__ float g_h0 [Bc*Dc];
__device__ float g_f0 [Bc*Dc];
__device__ float g_m0 [Bc*Fc];

__device__ __forceinline__ float gelu_exact(float x) {
    return 0.5f * x * (1.0f + erff(x * 0.70710678118654752f));
}

__device__ __forceinline__ uint32_t f2tf32(float x) {
    uint32_t r;
    asm("cvt.rna.tf32.f32 %0, %1;" : "=r"(r) : "f"(x));
    return r;
}

__device__ __forceinline__ void mma_tf32(float* c,
    uint32_t a0, uint32_t a1, uint32_t a2, uint32_t a3,
    uint32_t b0, uint32_t b1) {
    asm volatile(
        "mma.sync.aligned.m16n8k8.row.col.f32.tf32.tf32.f32 "
        "{%0,%1,%2,%3}, {%4,%5,%6,%7}, {%8,%9}, {%0,%1,%2,%3};"
        : "+f"(c[0]), "+f"(c[1]), "+f"(c[2]), "+f"(c[3])
        : "r"(a0), "r"(a1), "r"(a2), "r"(a3), "r"(b0), "r"(b1));
}

// ---------------- embedding gather ----------------
__global__ void embed_gather(const int* __restrict__ ids, const float* __restrict__ tok,
                             const float* __restrict__ pos, float* __restrict__ out) {
    long i = (long)blockIdx.x * 256 + threadIdx.x;
    if (i >= (long)Bc*Sc*Dc) return;
    long bs = i / Dc; int d = (int)(i % Dc); int s = (int)(bs % Sc);
    out[i] = tok[(size_t)ids[bs]*Dc + d] + pos[(size_t)s*Dc + d];
}

// ---------------- LayerNorm (+optional residual); one block per row, D=768 ----------------
__global__ void ln_kernel(const float* __restrict__ x, long xs,
                          const float* __restrict__ res, long rs,
                          const float* __restrict__ g, const float* __restrict__ bb,
                          float* __restrict__ out, long os) {
    __shared__ float red[256];
    int row = blockIdx.x, t = threadIdx.x;
    const float* xr = x + (size_t)row * xs;
    float v0 = xr[t], v1 = xr[t+256], v2 = xr[t+512];
    if (res) {
        const float* rr = res + (size_t)row * rs;
        v0 += rr[t]; v1 += rr[t+256]; v2 += rr[t+512];
    }
    float s = v0 + v1 + v2;
    red[t] = s; __syncthreads();
    for (int o = 128; o > 0; o >>= 1) { if (t < o) red[t] += red[t+o]; __syncthreads(); }
    float mean = red[0] * (1.0f/768.0f); __syncthreads();
    float d0 = v0-mean, d1 = v1-mean, d2 = v2-mean;
    red[t] = d0*d0 + d1*d1 + d2*d2; __syncthreads();
    for (int o = 128; o > 0; o >>= 1) { if (t < o) red[t] += red[t+o]; __syncthreads(); }
    float rstd = rsqrtf(red[0] * (1.0f/768.0f) + 1e-5f);
    float* orow = out + (size_t)row * os;
    orow[t]     = d0*rstd*g[t]     + bb[t];
    orow[t+256] = d1*rstd*g[t+256] + bb[t+256];
    orow[t+512] = d2*rstd*g[t+512] + bb[t+512];
}

// ---------------- tf32 tensor-core GEMM, double-buffered smem ----------------
// 128x128x32 tile, 256 threads (8 warps 2x4), warp tile 64x32 via m16n8k8.
// dynamic smem: As[2][128][36] + Bs[2][32][136]  (A stride ==4 mod 32, B ==8 mod 32)
#define GEMM_SMEM ((2*128*36 + 2*32*136)*4)
__global__ __launch_bounds__(256, 2)
void gemm_tc_kernel(const float* __restrict__ A, const float* __restrict__ Wm,
                    const float* __restrict__ bias, float* __restrict__ Cout,
                    int M, int N, int K, float alpha, int act) {
    extern __shared__ uint32_t smg[];
    uint32_t (*As)[128][36] = (uint32_t(*)[128][36])smg;
    uint32_t (*Bs)[32][136] = (uint32_t(*)[32][136])(smg + 2*128*36);

    int t = threadIdx.x;
    int lane = t & 31, warp = t >> 5;
    int gid = lane >> 2, tig = lane & 3;
    int wm = (warp >> 2) * 64;
    int wn = (warp & 3) * 32;
    int bm = blockIdx.y * 128, bn = blockIdx.x * 128;

    float acc[4][4][4];
    #pragma unroll
    for (int i = 0; i < 4; i++)
        #pragma unroll
        for (int j = 0; j < 4; j++)
            #pragma unroll
            for (int r = 0; r < 4; r++) acc[i][j][r] = 0.f;

    int arow = t >> 3;          // 0..31
    int acol = (t & 7) * 4;     // 0..28
    int brow = t >> 5;          // 0..7
    int bcol = (t & 31) * 4;    // 0..124

    float4 pa[4], pb[4];
    #pragma unroll
    for (int r = 0; r < 4; r++)
        pa[r] = *(const float4*)(A + (size_t)(bm + arow + r*32)*K + acol);
    #pragma unroll
    for (int r = 0; r < 4; r++)
        pb[r] = *(const float4*)(Wm + (size_t)(brow + r*8)*N + bn + bcol);

    // store tile 0 into stage 0
    #pragma unroll
    for (int r = 0; r < 4; r++) {
        As[0][arow + r*32][acol+0] = f2tf32(pa[r].x);
        As[0][arow + r*32][acol+1] = f2tf32(pa[r].y);
        As[0][arow + r*32][acol+2] = f2tf32(pa[r].z);
        As[0][arow + r*32][acol+3] = f2tf32(pa[r].w);
        uint4 bw;
        bw.x = f2tf32(pb[r].x); bw.y = f2tf32(pb[r].y);
        bw.z = f2tf32(pb[r].z); bw.w = f2tf32(pb[r].w);
        *(uint4*)&Bs[0][brow + r*8][bcol] = bw;
    }
    __syncthreads();

    int KT = K >> 5;
    for (int kt = 0; kt < KT; kt++) {
        int cur = kt & 1, nxt = cur ^ 1;
        bool more = (kt + 1 < KT);
        if (more) {
            int k0 = (kt + 1) * 32;
            #pragma unroll
            for (int r = 0; r < 4; r++)
                pa[r] = *(const float4*)(A + (size_t)(bm + arow + r*32)*K + k0 + acol);
            #pragma unroll
            for (int r = 0; r < 4; r++)
                pb[r] = *(const float4*)(Wm + (size_t)(k0 + brow + r*8)*N + bn + bcol);
        }
        #pragma unroll
        for (int ks = 0; ks < 4; ks++) {
            int kk = ks * 8;
            uint32_t af[4][4], bf[4][2];
            #pragma unroll
            for (int mi = 0; mi < 4; mi++) {
                int m = wm + mi*16 + gid;
                af[mi][0] = As[cur][m    ][kk + tig];
                af[mi][1] = As[cur][m + 8][kk + tig];
                af[mi][2] = As[cur][m    ][kk + tig + 4];
                af[mi][3] = As[cur][m + 8][kk + tig + 4];
            }
            #pragma unroll
            for (int ni = 0; ni < 4; ni++) {
                int n = wn + ni*8 + gid;
                bf[ni][0] = Bs[cur][kk + tig    ][n];
                bf[ni][1] = Bs[cur][kk + tig + 4][n];
            }
            #pragma unroll
            for (int mi = 0; mi < 4; mi++)
                #pragma unroll
                for (int ni = 0; ni < 4; ni++)
                    mma_tf32(acc[mi][ni], af[mi][0], af[mi][1], af[mi][2], af[mi][3],
                             bf[ni][0], bf[ni][1]);
        }
        if (more) {
            #pragma unroll
            for (int r = 0; r < 4; r++) {
                As[nxt][arow + r*32][acol+0] = f2tf32(pa[r].x);
                As[nxt][arow + r*32][acol+1] = f2tf32(pa[r].y);
                As[nxt][arow + r*32][acol+2] = f2tf32(pa[r].z);
                As[nxt][arow + r*32][acol+3] = f2tf32(pa[r].w);
                uint4 bw;
                bw.x = f2tf32(pb[r].x); bw.y = f2tf32(pb[r].y);
                bw.z = f2tf32(pb[r].z); bw.w = f2tf32(pb[r].w);
                *(uint4*)&Bs[nxt][brow + r*8][bcol] = bw;
            }
        }
        __syncthreads();
    }

    #pragma unroll
    for (int mi = 0; mi < 4; mi++) {
        #pragma unroll
        for (int ni = 0; ni < 4; ni++) {
            int col = bn + wn + ni*8 + 2*tig;
            float b0v = bias[col], b1v = bias[col+1];
            #pragma unroll
            for (int half = 0; half < 2; half++) {
                int row = bm + wm + mi*16 + gid + half*8;
                float v0 = alpha * (acc[mi][ni][half*2+0] + b0v);
                float v1 = alpha * (acc[mi][ni][half*2+1] + b1v);
                if (act) { v0 = gelu_exact(v0); v1 = gelu_exact(v1); }
                float2 o; o.x = v0; o.y = v1;
                *(float2*)(Cout + (size_t)row*N + col) = o;
            }
        }
    }
}

// ---------------- fused sliding-window attention (flash-style, tf32 mma) ----------
// block = 256 thr (8 warps), handles 128 query rows of one (b,h,n) block-half.
// key window [s_base-256, s_base+384) in 10 chunks of 64. Online softmax.
// Global key 0 folded into the epilogue. Writes ctx directly.
// dyn smem: Qs[128][68] Ps[128][68] Ks[64][68] Vs[64][72] + kval[64]+v0[64]
#define ATT_SMEM ((2*128*68 + 64*68 + 64*72 + 128)*4)
__global__ __launch_bounds__(256, 2)
void fused_attn_kernel(const float* __restrict__ q, const float* __restrict__ k,
                       const float* __restrict__ v, const int* __restrict__ mask,
                       float* __restrict__ ctx) {
    extern __shared__ uint32_t sma[];
    uint32_t (*Qs)[68] = (uint32_t(*)[68])sma;
    uint32_t (*Ps)[68] = (uint32_t(*)[68])(sma + 128*68);
    uint32_t (*Ks)[68] = (uint32_t(*)[68])(sma + 2*128*68);
    uint32_t (*Vs)[72] = (uint32_t(*)[72])(sma + 2*128*68 + 64*68);
    float* kval = (float*)(sma + 2*128*68 + 64*68 + 64*72);
    float* v0s  = kval + 64;

    int half = blockIdx.x, n = blockIdx.y;
    int bh = blockIdx.z; int hh = bh % Hc; int b = bh / Hc;
    int s_base = n*Cc + half*128;
    int jg0 = s_base - 256;

    int t = threadIdx.x, lane = t & 31, w = t >> 5;
    int gid = lane >> 2, tig = lane & 3;
    int wm = w * 16;

    // load Q tile (128 x 64) as tf32
    {
        int c4 = (t & 15) * 4;
        #pragma unroll
        for (int r = 0; r < 8; r++) {
            int row = r*16 + (t >> 4);
            float4 qv = *(const float4*)(q + ((size_t)(b*Sc + s_base + row))*Dc + hh*64 + c4);
            Qs[row][c4+0] = f2tf32(qv.x); Qs[row][c4+1] = f2tf32(qv.y);
            Qs[row][c4+2] = f2tf32(qv.z); Qs[row][c4+3] = f2tf32(qv.w);
        }
    }
    if (t < 16) {
        float4 vv = *(const float4*)(v + ((size_t)b*Sc)*Dc + hh*64 + t*4);
        v0s[t*4+0] = vv.x; v0s[t*4+1] = vv.y; v0s[t*4+2] = vv.z; v0s[t*4+3] = vv.w;
    }

    float m0 = -1e30f, m1 = -1e30f, l0 = 0.f, l1 = 0.f;
    float ov[8][4];
    #pragma unroll
    for (int i = 0; i < 8; i++)
        #pragma unroll
        for (int r = 0; r < 4; r++) ov[i][r] = 0.f;

    int s0 = s_base + wm + gid, s1 = s0 + 8;

    for (int ch = 0; ch < 10; ch++) {
        int jgc = jg0 + ch*64;
        if (jgc + 64 <= 1 || jgc >= Sc) continue;   // uniform per block
        __syncthreads();
        // load K/V chunk (64 x 64) + key-valid flags
        {
            int c4 = (t & 15) * 4;
            #pragma unroll
            for (int r = 0; r < 4; r++) {
                int row = r*16 + (t >> 4);
                int jg = jgc + row;
                float4 kv = make_float4(0.f,0.f,0.f,0.f);
                float4 vv = make_float4(0.f,0.f,0.f,0.f);
                if (jg >= 0 && jg < Sc) {
                    kv = *(const float4*)(k + ((size_t)(b*Sc + jg))*Dc + hh*64 + c4);
                    vv = *(const float4*)(v + ((size_t)(b*Sc + jg))*Dc + hh*64 + c4);
                }
                Ks[row][c4+0] = f2tf32(kv.x); Ks[row][c4+1] = f2tf32(kv.y);
                Ks[row][c4+2] = f2tf32(kv.z); Ks[row][c4+3] = f2tf32(kv.w);
                Vs[row][c4+0] = f2tf32(vv.x); Vs[row][c4+1] = f2tf32(vv.y);
                Vs[row][c4+2] = f2tf32(vv.z); Vs[row][c4+3] = f2tf32(vv.w);
            }
            if (t < 64) {
                int jg = jgc + t;
                kval[t] = (jg >= 1 && jg < Sc && mask[(size_t)b*Sc + jg] > 0) ? 1.f : 0.f;
            }
        }
        __syncthreads();

        // S = Q @ K^T  (16 x 64 per warp)
        float sc[8][4];
        #pragma unroll
        for (int i = 0; i < 8; i++)
            #pragma unroll
            for (int r = 0; r < 4; r++) sc[i][r] = 0.f;
        #pragma unroll
        for (int ks = 0; ks < 8; ks++) {
            int kk = ks * 8;
            uint32_t a0 = Qs[wm + gid    ][kk + tig];
            uint32_t a1 = Qs[wm + gid + 8][kk + tig];
            uint32_t a2 = Qs[wm + gid    ][kk + tig + 4];
            uint32_t a3 = Qs[wm + gid + 8][kk + tig + 4];
            #pragma unroll
            for (int ni = 0; ni < 8; ni++) {
                uint32_t b0 = Ks[ni*8 + gid][kk + tig];
                uint32_t b1 = Ks[ni*8 + gid][kk + tig + 4];
                mma_tf32(sc[ni], a0, a1, a2, a3, b0, b1);
            }
        }

        // mask + online softmax
        float cm0 = -1e30f, cm1 = -1e30f;
        unsigned vb0 = 0, vb1 = 0;
        #pragma unroll
        for (int ni = 0; ni < 8; ni++) {
            #pragma unroll
            for (int e = 0; e < 2; e++) {
                int col = ni*8 + 2*tig + e;
                int jg = jgc + col;
                bool kv_ok = kval[col] > 0.5f;
                if (kv_ok && jg >= s0-256 && jg <= s0+256) {
                    cm0 = fmaxf(cm0, sc[ni][e]); vb0 |= 1u << (ni*2+e);
                }
                if (kv_ok && jg >= s1-256 && jg <= s1+256) {
                    cm1 = fmaxf(cm1, sc[ni][2+e]); vb1 |= 1u << (ni*2+e);
                }
            }
        }
        cm0 = fmaxf(cm0, __shfl_xor_sync(0xffffffffu, cm0, 1));
        cm0 = fmaxf(cm0, __shfl_xor_sync(0xffffffffu, cm0, 2));
        cm1 = fmaxf(cm1, __shfl_xor_sync(0xffffffffu, cm1, 1));
        cm1 = fmaxf(cm1, __shfl_xor_sync(0xffffffffu, cm1, 2));
        float nm0 = fmaxf(m0, cm0), nm1 = fmaxf(m1, cm1);
        float sc0 = expf(m0 - nm0), sc1 = expf(m1 - nm1);
        m0 = nm0; m1 = nm1;
        float rs0 = 0.f, rs1 = 0.f;
        #pragma unroll
        for (int ni = 0; ni < 8; ni++) {
            #pragma unroll
            for (int e = 0; e < 2; e++) {
                int col = ni*8 + 2*tig + e;
                float p0 = (vb0 >> (ni*2+e)) & 1 ? expf(sc[ni][e]   - nm0) : 0.f;
                float p1 = (vb1 >> (ni*2+e)) & 1 ? expf(sc[ni][2+e] - nm1) : 0.f;
                rs0 += p0; rs1 += p1;
                Ps[wm + gid    ][col] = f2tf32(p0);
                Ps[wm + gid + 8][col] = f2tf32(p1);
            }
        }
        rs0 += __shfl_xor_sync(0xffffffffu, rs0, 1);
        rs0 += __shfl_xor_sync(0xffffffffu, rs0, 2);
        rs1 += __shfl_xor_sync(0xffffffffu, rs1, 1);
        rs1 += __shfl_xor_sync(0xffffffffu, rs1, 2);
        l0 = l0*sc0 + rs0; l1 = l1*sc1 + rs1;
        #pragma unroll
        for (int ni = 0; ni < 8; ni++) {
            ov[ni][0] *= sc0; ov[ni][1] *= sc0;
            ov[ni][2] *= sc1; ov[ni][3] *= sc1;
        }
        __syncwarp();

        // O += P @ V  (16 x 64 per warp)
        #pragma unroll
        for (int ks = 0; ks < 8; ks++) {
            int kk = ks * 8;
            uint32_t a0 = Ps[wm + gid    ][kk + tig];
            uint32_t a1 = Ps[wm + gid + 8][kk + tig];
            uint32_t a2 = Ps[wm + gid    ][kk + tig + 4];
            uint32_t a3 = Ps[wm + gid + 8][kk + tig + 4];
            #pragma unroll
            for (int ni = 0; ni < 8; ni++) {
                uint32_t b0 = Vs[kk + tig    ][ni*8 + gid];
                uint32_t b1 = Vs[kk + tig + 4][ni*8 + gid];
                mma_tf32(ov[ni], a0, a1, a2, a3, b0, b1);
            }
        }
    }

    // epilogue: global key 0 column + normalize + store
    const float* k0p = k + ((size_t)b*Sc)*Dc + hh*64;
    const float* q0p = q + ((size_t)(b*Sc + s0))*Dc + hh*64;
    const float* q1p = q + ((size_t)(b*Sc + s1))*Dc + hh*64;
    float gp0 = 0.f, gp1 = 0.f;
    #pragma unroll
    for (int i = 0; i < 16; i++) {
        int d = tig*16 + i;
        float kv = k0p[d];
        gp0 += q0p[d]*kv;
        gp1 += q1p[d]*kv;
    }
    gp0 += __shfl_xor_sync(0xffffffffu, gp0, 1);
    gp0 += __shfl_xor_sync(0xffffffffu, gp0, 2);
    gp1 += __shfl_xor_sync(0xffffffffu, gp1, 1);
    gp1 += __shfl_xor_sync(0xffffffffu, gp1, 2);
    bool gok = mask[(size_t)b*Sc] > 0;
    float mf0 = gok ? fmaxf(m0, gp0) : m0;
    float mf1 = gok ? fmaxf(m1, gp1) : m1;
    float e0c = expf(m0 - mf0), e1c = expf(m1 - mf1);
    float eg0 = gok ? expf(gp0 - mf0) : 0.f;
    float eg1 = gok ? expf(gp1 - mf1) : 0.f;
    float inv0 = 1.f / (l0*e0c + eg0);
    float inv1 = 1.f / (l1*e1c + eg1);
    #pragma unroll
    for (int ni = 0; ni < 8; ni++) {
        int colb = ni*8 + 2*tig;
        float gv0 = v0s[colb], gv1 = v0s[colb+1];
        float2 o0v, o1v;
        o0v.x = (ov[ni][0]*e0c + eg0*gv0) * inv0;
        o0v.y = (ov[ni][1]*e0c + eg0*gv1) * inv0;
        o1v.x = (ov[ni][2]*e1c + eg1*gv0) * inv1;
        o1v.y = (ov[ni][3]*e1c + eg1*gv1) * inv1;
        *(float2*)(ctx + ((size_t)(b*Sc + s0))*Dc + hh*64 + colb) = o0v;
        *(float2*)(ctx + ((size_t)(b*Sc + s1))*Dc + hh*64 + colb) = o1v;
    }
}

// ---------------- full-attention row 0 (global token) ----------------
__global__ void attn_row0_kernel(const float* __restrict__ q0base, long q_bs,
                                 const float* __restrict__ k, const float* __restrict__ v,
                                 const int* __restrict__ mask,
                                 float* __restrict__ outbase, long out_bs) {
    int hh = blockIdx.x, b = blockIdx.y;
    __shared__ float sc[Sc];
    __shared__ float q0s[64];
    __shared__ float red[256];
    __shared__ float part[4][64];
    int tid = threadIdx.x;
    if (tid < 16)
        ((float4*)q0s)[tid] = *(const float4*)(q0base + (size_t)b*q_bs + hh*64 + tid*4);
    __syncthreads();
    float lmax = NEGF;
    for (int it = 0; it < Sc/256; it++) {
        int j = tid + 256*it;
        const float4* kr = (const float4*)(k + ((size_t)(b*Sc + j))*Dc + hh*64);
        float s = 0.f;
        #pragma unroll
        for (int d4 = 0; d4 < 16; d4++) {
            float4 kv = kr[d4]; float4 qv = ((const float4*)q0s)[d4];
            s += kv.x*qv.x + kv.y*qv.y + kv.z*qv.z + kv.w*qv.w;
        }
        if (mask[b*Sc + j] <= 0) s = NEGF;
        sc[j] = s;
        lmax = fmaxf(lmax, s);
    }
    red[tid] = lmax; __syncthreads();
    for (int o = 128; o > 0; o >>= 1) { if (tid < o) red[tid] = fmaxf(red[tid], red[tid+o]); __syncthreads(); }
    float M = red[0]; __syncthreads();
    float lsum = 0.f;
    for (int it = 0; it < Sc/256; it++) {
        int j = tid + 256*it;
        float e = expf(sc[j] - M);
        sc[j] = e; lsum += e;
    }
    red[tid] = lsum; __syncthreads();
    for (int o = 128; o > 0; o >>= 1) { if (tid < o) red[tid] += red[tid+o]; __syncthreads(); }
    float inv = 1.0f / red[0];
    __syncthreads();
    int d = tid & 63, p = tid >> 6;
    float accd = 0.f;
    for (int j = p; j < Sc; j += 4)
        accd += sc[j] * v[((size_t)(b*Sc + j))*Dc + hh*64 + d];
    part[p][d] = accd;
    __syncthreads();
    if (tid < 64) {
        float o = (part[0][tid] + part[1][tid] + part[2][tid] + part[3][tid]) * inv;
        outbase[(size_t)b*out_bs + hh*64 + tid] = o;
    }
}

// ---------------- single-row GEMM ----------------
__global__ void row_gemm_kernel(const float* __restrict__ x, long x_bs,
                                const float* __restrict__ Wm, const float* __restrict__ bias,
                                float* __restrict__ out, long out_bs,
                                int K, int N, float alpha, int act) {
    extern __shared__ float xs[];
    int b = blockIdx.y;
    for (int i = threadIdx.x; i < K; i += 256) xs[i] = x[(size_t)b*x_bs + i];
    __syncthreads();
    int n = blockIdx.x*256 + threadIdx.x;
    if (n < N) {
        float acc = 0.f;
        for (int kk = 0; kk < K; kk++) acc += xs[kk] * Wm[(size_t)kk*N + n];
        float vv = alpha * (acc + bias[n]);
        if (act) vv = gelu_exact(vv);
        out[(size_t)b*out_bs + n] = vv;
    }
}

// =======================================================================
extern "C" void kernel_launch(void* const* d_in, const int* in_sizes, int n_in,
                              void* d_out, int out_size) {
    const int*   ids   = (const int*)d_in[0];
    const int*   mask  = (const int*)d_in[1];
    const float* etok  = (const float*)d_in[2];
    const float* epos  = (const float*)d_in[3];
    const float* eg    = (const float*)d_in[4];
    const float* ebv   = (const float*)d_in[5];
    const float* Wq    = (const float*)d_in[6];
    const float* bq    = (const float*)d_in[7];
    const float* Wk    = (const float*)d_in[8];
    const float* bk    = (const float*)d_in[9];
    const float* Wv    = (const float*)d_in[10];
    const float* bv    = (const float*)d_in[11];
    const float* Wo    = (const float*)d_in[12];
    const float* bo    = (const float*)d_in[13];
    const float* ln1g  = (const float*)d_in[14];
    const float* ln1b  = (const float*)d_in[15];
    const float* W1    = (const float*)d_in[16];
    const float* b1    = (const float*)d_in[17];
    const float* W2    = (const float*)d_in[18];
    const float* b2    = (const float*)d_in[19];
    const float* ln2g  = (const float*)d_in[20];
    const float* ln2b  = (const float*)d_in[21];
    const float* clsW  = (const float*)d_in[22];
    const float* clsb  = (const float*)d_in[23];
    float* out = (float*)d_out;

    float *h,*q,*k,*v,*ctx,*att,*mid,*q0,*o0,*a0,*h0,*f0,*m0;
    cudaGetSymbolAddress((void**)&h,   g_h);
    cudaGetSymbolAddress((void**)&q,   g_q);
    cudaGetSymbolAddress((void**)&k,   g_k);
    cudaGetSymbolAddress((void**)&v,   g_v);
    cudaGetSymbolAddress((void**)&ctx, g_ctx);
    cudaGetSymbolAddress((void**)&att, g_att);
    cudaGetSymbolAddress((void**)&mid, g_mid);
    cudaGetSymbolAddress((void**)&q0,  g_q0);
    cudaGetSymbolAddress((void**)&o0,  g_o0);
    cudaGetSymbolAddress((void**)&a0,  g_a0);
    cudaGetSymbolAddress((void**)&h0,  g_h0);
    cudaGetSymbolAddress((void**)&f0,  g_f0);
    cudaGetSymbolAddress((void**)&m0,  g_m0);

    cudaFuncSetAttribute(gemm_tc_kernel,
        cudaFuncAttributeMaxDynamicSharedMemorySize, GEMM_SMEM);
    cudaFuncSetAttribute(fused_attn_kernel,
        cudaFuncAttributeMaxDynamicSharedMemorySize, ATT_SMEM);

    const int M = Bc*Sc;                 // 8192
    dim3 gD(Dc/128, M/128);              // (6, 64)
    dim3 gF(Fc/128, M/128);              // (24, 64)

    // ---- embeddings ----
    embed_gather<<<(Bc*Sc*Dc + 255)/256, 256>>>(ids, etok, epos, ctx);
    ln_kernel<<<M, 256>>>(ctx, Dc, nullptr, 0, eg, ebv, h, Dc);

    // ---- layer 0 (full) ----
    gemm_tc_kernel<<<gD, 256, GEMM_SMEM>>>(h, Wq, bq, q, M, Dc, Dc, 0.125f, 0);
    gemm_tc_kernel<<<gD, 256, GEMM_SMEM>>>(h, Wk, bk, k, M, Dc, Dc, 1.0f, 0);
    gemm_tc_kernel<<<gD, 256, GEMM_SMEM>>>(h, Wv, bv, v, M, Dc, Dc, 1.0f, 0);
    fused_attn_kernel<<<dim3(2, NBc, Bc*Hc), 256, ATT_SMEM>>>(q, k, v, mask, ctx);
    attn_row0_kernel<<<dim3(Hc, Bc), 256>>>(q, (long)Sc*Dc, k, v, mask, ctx, (long)Sc*Dc);
    gemm_tc_kernel<<<gD, 256, GEMM_SMEM>>>(ctx, Wo, bo, att, M, Dc, Dc, 1.0f, 0);
    ln_kernel<<<M, 256>>>(h, Dc, att, Dc, ln1g, ln1b, h, Dc);
    gemm_tc_kernel<<<gF, 256, GEMM_SMEM>>>(h, W1, b1, mid, M, Fc, Dc, 1.0f, 1);
    gemm_tc_kernel<<<gD, 256, GEMM_SMEM>>>(mid, W2, b2, att, M, Dc, Fc, 1.0f, 0);
    ln_kernel<<<M, 256>>>(h, Dc, att, Dc, ln2g, ln2b, h, Dc);

    // ---- layer 1 (pruned: only position 0 survives to the classifier) ----
    const float* Wq1 = Wq + (size_t)Dc*Dc; const float* bq1 = bq + Dc;
    const float* Wk1 = Wk + (size_t)Dc*Dc; const float* bk1 = bk + Dc;
    const float* Wv1 = Wv + (size_t)Dc*Dc; const float* bv1 = bv + Dc;
    const float* Wo1 = Wo + (size_t)Dc*Dc; const float* bo1 = bo + Dc;
    const float* W11 = W1 + (size_t)Dc*Fc; const float* b11 = b1 + Fc;
    const float* W21 = W2 + (size_t)Fc*Dc; const float* b21 = b2 + Dc;

    gemm_tc_kernel<<<gD, 256, GEMM_SMEM>>>(h, Wk1, bk1, k, M, Dc, Dc, 1.0f, 0);
    gemm_tc_kernel<<<gD, 256, GEMM_SMEM>>>(h, Wv1, bv1, v, M, Dc, Dc, 1.0f, 0);
    row_gemm_kernel<<<dim3(Dc/256, Bc), 256, Dc*sizeof(float)>>>(
        h, (long)Sc*Dc, Wq1, bq1, q0, Dc, Dc, Dc, 0.125f, 0);
    attn_row0_kernel<<<dim3(Hc, Bc), 256>>>(q0, (long)Dc, k, v, mask, o0, (long)Dc);
    row_gemm_kernel<<<dim3(Dc/256, Bc), 256, Dc*sizeof(float)>>>(
        o0, (long)Dc, Wo1, bo1, a0, Dc, Dc, Dc, 1.0f, 0);
    ln_kernel<<<Bc, 256>>>(h, (long)Sc*Dc, a0, Dc, ln1g + Dc, ln1b + Dc, h0, Dc);
    row_gemm_kernel<<<dim3(Fc/256, Bc), 256, Dc*sizeof(float)>>>(
        h0, (long)Dc, W11, b11, m0, Fc, Dc, Fc, 1.0f, 1);
    row_gemm_kernel<<<dim3(Dc/256, Bc), 256, Fc*sizeof(float)>>>(
        m0, (long)Fc, W21, b21, f0, Dc, Fc, Dc, 1.0f, 0);
    ln_kernel<<<Bc, 256>>>(h0, Dc, f0, Dc, ln2g + Dc, ln2b + Dc, h0, Dc);
    row_gemm_kernel<<<dim3(1, Bc), 256, Dc*sizeof(float)>>>(
        h0, (long)Dc, clsW, clsb, out, 3, Dc, 3, 1.0f, 0);
}